// round 1
// baseline (speedup 1.0000x reference)
#include <cuda_runtime.h>
#include <cstdint>
#include <cstddef>

#define B_SZ   4
#define SEQ    2048
#define DMODEL 1024
#define NHEADS 16
#define DHEAD  64
#define NPHYS  8
#define MTOK   (B_SZ * SEQ)      // 8192

// Scratch (allocation-free rule: __device__ globals)
__device__ float g_qkv[(size_t)MTOK * 3 * DMODEL];   // [B*N, 3072]
__device__ float g_att[(size_t)MTOK * DMODEL];       // [B*N, 1024]

__device__ __forceinline__ uint32_t f2tf(float x) {
    uint32_t y;
    asm("cvt.rna.tf32.f32 %0, %1;" : "=r"(y) : "f"(x));
    return y;
}

__device__ __forceinline__ void mma_tf32(float* c, const uint32_t* a, const uint32_t* b) {
    asm volatile(
        "mma.sync.aligned.m16n8k8.row.col.f32.tf32.tf32.f32 "
        "{%0,%1,%2,%3}, {%4,%5,%6,%7}, {%8,%9}, {%0,%1,%2,%3};\n"
        : "+f"(c[0]), "+f"(c[1]), "+f"(c[2]), "+f"(c[3])
        : "r"(a[0]), "r"(a[1]), "r"(a[2]), "r"(a[3]), "r"(b[0]), "r"(b[1]));
}

// ============================================================================
// GEMM: C[M, Nout] = A[M, 1024] @ W[Nout, 1024]^T   (tf32 mma, fp32 accum)
// Block tile 128x64, BK=32, 256 threads (8 warps = 4m x 2n), warp tile 32x32.
// ============================================================================
#define GBM 128
#define GBN 64
#define GBK 32
#define GST 36   // smem row stride (pad 4, keeps 16B alignment, kills conflicts)

__global__ __launch_bounds__(256) void gemm_tf32_kernel(
    const float* __restrict__ A, const float* __restrict__ W,
    float* __restrict__ C, int Nout)
{
    __shared__ uint32_t As[GBM][GST];
    __shared__ uint32_t Ws[GBN][GST];

    const int tid  = threadIdx.x;
    const int lane = tid & 31;
    const int warp = tid >> 5;
    const int wm   = warp & 3;       // 0..3
    const int wn   = warp >> 2;      // 0..1
    const int bm   = blockIdx.x * GBM;
    const int bn   = blockIdx.y * GBN;
    const int rl   = lane >> 2;      // 0..7
    const int qd   = lane & 3;       // 0..3

    float c[2][4][4];
    #pragma unroll
    for (int i = 0; i < 2; i++)
        #pragma unroll
        for (int j = 0; j < 4; j++)
            #pragma unroll
            for (int k = 0; k < 4; k++) c[i][j][k] = 0.f;

    for (int k0 = 0; k0 < DMODEL; k0 += GBK) {
        // A tile: 128x32 = 1024 float4, 4 per thread
        #pragma unroll
        for (int i = 0; i < 4; i++) {
            int idx = tid + i * 256;
            int r = idx >> 3, c4 = (idx & 7) << 2;
            float4 v = *(const float4*)&A[(size_t)(bm + r) * DMODEL + k0 + c4];
            As[r][c4 + 0] = f2tf(v.x); As[r][c4 + 1] = f2tf(v.y);
            As[r][c4 + 2] = f2tf(v.z); As[r][c4 + 3] = f2tf(v.w);
        }
        // W tile: 64x32 = 512 float4, 2 per thread
        #pragma unroll
        for (int i = 0; i < 2; i++) {
            int idx = tid + i * 256;
            int r = idx >> 3, c4 = (idx & 7) << 2;
            float4 v = *(const float4*)&W[(size_t)(bn + r) * DMODEL + k0 + c4];
            Ws[r][c4 + 0] = f2tf(v.x); Ws[r][c4 + 1] = f2tf(v.y);
            Ws[r][c4 + 2] = f2tf(v.z); Ws[r][c4 + 3] = f2tf(v.w);
        }
        __syncthreads();

        #pragma unroll
        for (int ks = 0; ks < 4; ks++) {
            uint32_t a[2][4], b[4][2];
            const int cc = ks * 8 + qd;
            #pragma unroll
            for (int tm = 0; tm < 2; tm++) {
                int r0 = wm * 32 + tm * 16 + rl;
                a[tm][0] = As[r0][cc];     a[tm][1] = As[r0 + 8][cc];
                a[tm][2] = As[r0][cc + 4]; a[tm][3] = As[r0 + 8][cc + 4];
            }
            #pragma unroll
            for (int tn = 0; tn < 4; tn++) {
                int r = wn * 32 + tn * 8 + rl;
                b[tn][0] = Ws[r][cc]; b[tn][1] = Ws[r][cc + 4];
            }
            #pragma unroll
            for (int tm = 0; tm < 2; tm++)
                #pragma unroll
                for (int tn = 0; tn < 4; tn++)
                    mma_tf32(c[tm][tn], a[tm], b[tn]);
        }
        __syncthreads();
    }

    #pragma unroll
    for (int tm = 0; tm < 2; tm++) {
        int r0 = bm + wm * 32 + tm * 16 + rl;
        #pragma unroll
        for (int tn = 0; tn < 4; tn++) {
            int col = bn + wn * 32 + tn * 8 + (qd << 1);
            *(float2*)&C[(size_t)r0 * Nout + col]       = make_float2(c[tm][tn][0], c[tm][tn][1]);
            *(float2*)&C[(size_t)(r0 + 8) * Nout + col] = make_float2(c[tm][tn][2], c[tm][tn][3]);
        }
    }
}

// ============================================================================
// Fused flash attention. One block = (b, h, 64 query rows). 128 threads.
// Warp w owns rows [w*16, w*16+16). Br = Bc = 64, dh = 64.
// S = (Q K^T)*scale (+ beta*bias for h<8) -> online softmax -> O += P V.
// P is staged through warp-private SMEM to convert C-frag -> A-frag layout.
// ============================================================================
#define ASTRIDE 68
#define ATT_SMEM (4 * 64 * ASTRIDE * 4)   // Qs, Ks, Vs, Ps  (69632 B)

__global__ __launch_bounds__(128) void attn_kernel(
    const float* __restrict__ qkv, const float* __restrict__ bias,
    const float* __restrict__ beta, float* __restrict__ attn_out)
{
    extern __shared__ uint32_t smx[];
    uint32_t* Qs = smx;
    uint32_t* Ks = smx + 64 * ASTRIDE;
    uint32_t* Vs = smx + 2 * 64 * ASTRIDE;
    uint32_t* Ps = smx + 3 * 64 * ASTRIDE;

    const int tid  = threadIdx.x;
    const int lane = tid & 31;
    const int warp = tid >> 5;
    const int rl   = lane >> 2;   // 0..7
    const int qd   = lane & 3;    // 0..3
    const int rt   = blockIdx.x;  // query row tile (0..31)
    const int h    = blockIdx.y;
    const int b    = blockIdx.z;
    const int row0g = rt * 64;

    const bool usebias = (h < NPHYS);
    const float betah  = usebias ? beta[h] : 0.f;
    const float scale  = 0.125f;   // 1/sqrt(64)

    // Load Q tile (64x64) once
    const float* qbase = qkv + ((size_t)(b * SEQ + row0g)) * 3072 + h * 64;
    #pragma unroll
    for (int i = 0; i < 8; i++) {
        int idx = tid + i * 128;
        int r = idx >> 4, c4 = (idx & 15) << 2;
        float4 v = *(const float4*)&qbase[(size_t)r * 3072 + c4];
        Qs[r * ASTRIDE + c4 + 0] = f2tf(v.x); Qs[r * ASTRIDE + c4 + 1] = f2tf(v.y);
        Qs[r * ASTRIDE + c4 + 2] = f2tf(v.z); Qs[r * ASTRIDE + c4 + 3] = f2tf(v.w);
    }

    float o[8][4];
    #pragma unroll
    for (int tn = 0; tn < 8; tn++)
        #pragma unroll
        for (int i = 0; i < 4; i++) o[tn][i] = 0.f;
    float m0 = -1e30f, m1 = -1e30f, l0 = 0.f, l1 = 0.f;

    const int pr0 = warp * 16 + rl;   // this thread's low row within the 64-row tile

    for (int jt = 0; jt < 32; jt++) {
        __syncthreads();  // covers Q on first iter; guards K/V/Ps overwrite after

        const float* kbase = qkv + ((size_t)(b * SEQ + jt * 64)) * 3072 + 1024 + h * 64;
        const float* vbase = kbase + 1024;
        #pragma unroll
        for (int i = 0; i < 8; i++) {
            int idx = tid + i * 128;
            int r = idx >> 4, c4 = (idx & 15) << 2;
            float4 kv = *(const float4*)&kbase[(size_t)r * 3072 + c4];
            Ks[r * ASTRIDE + c4 + 0] = f2tf(kv.x); Ks[r * ASTRIDE + c4 + 1] = f2tf(kv.y);
            Ks[r * ASTRIDE + c4 + 2] = f2tf(kv.z); Ks[r * ASTRIDE + c4 + 3] = f2tf(kv.w);
            float4 vv = *(const float4*)&vbase[(size_t)r * 3072 + c4];
            Vs[r * ASTRIDE + c4 + 0] = f2tf(vv.x); Vs[r * ASTRIDE + c4 + 1] = f2tf(vv.y);
            Vs[r * ASTRIDE + c4 + 2] = f2tf(vv.z); Vs[r * ASTRIDE + c4 + 3] = f2tf(vv.w);
        }
        __syncthreads();

        // ---- S = Q K^T ----
        float s[8][4];
        #pragma unroll
        for (int tn = 0; tn < 8; tn++)
            #pragma unroll
            for (int i = 0; i < 4; i++) s[tn][i] = 0.f;

        #pragma unroll
        for (int ks = 0; ks < 8; ks++) {
            const int cc = ks * 8 + qd;
            uint32_t a[4];
            a[0] = Qs[pr0 * ASTRIDE + cc];       a[1] = Qs[(pr0 + 8) * ASTRIDE + cc];
            a[2] = Qs[pr0 * ASTRIDE + cc + 4];   a[3] = Qs[(pr0 + 8) * ASTRIDE + cc + 4];
            #pragma unroll
            for (int tn = 0; tn < 8; tn++) {
                uint32_t bb[2];
                int kr = tn * 8 + rl;
                bb[0] = Ks[kr * ASTRIDE + cc];
                bb[1] = Ks[kr * ASTRIDE + cc + 4];
                mma_tf32(s[tn], a, bb);
            }
        }

        // ---- scale + bias ----
        const int grow0 = row0g + warp * 16 + rl;
        if (usebias) {
            const float* bb0 = bias + ((size_t)b * SEQ + grow0) * SEQ + jt * 64;
            const float* bb1 = bb0 + (size_t)8 * SEQ;
            #pragma unroll
            for (int tn = 0; tn < 8; tn++) {
                int col = tn * 8 + (qd << 1);
                float2 x0 = *(const float2*)&bb0[col];
                float2 x1 = *(const float2*)&bb1[col];
                s[tn][0] = s[tn][0] * scale + betah * x0.x;
                s[tn][1] = s[tn][1] * scale + betah * x0.y;
                s[tn][2] = s[tn][2] * scale + betah * x1.x;
                s[tn][3] = s[tn][3] * scale + betah * x1.y;
            }
        } else {
            #pragma unroll
            for (int tn = 0; tn < 8; tn++)
                #pragma unroll
                for (int i = 0; i < 4; i++) s[tn][i] *= scale;
        }

        // ---- online softmax (rows rl and rl+8 of this warp's 16) ----
        float mx0 = -1e30f, mx1 = -1e30f;
        #pragma unroll
        for (int tn = 0; tn < 8; tn++) {
            mx0 = fmaxf(mx0, fmaxf(s[tn][0], s[tn][1]));
            mx1 = fmaxf(mx1, fmaxf(s[tn][2], s[tn][3]));
        }
        mx0 = fmaxf(mx0, __shfl_xor_sync(0xffffffffu, mx0, 1));
        mx0 = fmaxf(mx0, __shfl_xor_sync(0xffffffffu, mx0, 2));
        mx1 = fmaxf(mx1, __shfl_xor_sync(0xffffffffu, mx1, 1));
        mx1 = fmaxf(mx1, __shfl_xor_sync(0xffffffffu, mx1, 2));

        float mn0 = fmaxf(m0, mx0), mn1 = fmaxf(m1, mx1);
        float f0 = __expf(m0 - mn0), f1 = __expf(m1 - mn1);
        float sum0 = 0.f, sum1 = 0.f;
        #pragma unroll
        for (int tn = 0; tn < 8; tn++) {
            s[tn][0] = __expf(s[tn][0] - mn0);
            s[tn][1] = __expf(s[tn][1] - mn0);
            s[tn][2] = __expf(s[tn][2] - mn1);
            s[tn][3] = __expf(s[tn][3] - mn1);
            sum0 += s[tn][0] + s[tn][1];
            sum1 += s[tn][2] + s[tn][3];
        }
        sum0 += __shfl_xor_sync(0xffffffffu, sum0, 1);
        sum0 += __shfl_xor_sync(0xffffffffu, sum0, 2);
        sum1 += __shfl_xor_sync(0xffffffffu, sum1, 1);
        sum1 += __shfl_xor_sync(0xffffffffu, sum1, 2);
        l0 = l0 * f0 + sum0;
        l1 = l1 * f1 + sum1;
        m0 = mn0; m1 = mn1;
        #pragma unroll
        for (int tn = 0; tn < 8; tn++) {
            o[tn][0] *= f0; o[tn][1] *= f0;
            o[tn][2] *= f1; o[tn][3] *= f1;
        }

        // ---- stage P (C-frag layout -> SMEM -> A-frag layout), warp-private ----
        #pragma unroll
        for (int tn = 0; tn < 8; tn++) {
            int col = tn * 8 + (qd << 1);
            Ps[pr0 * ASTRIDE + col]           = f2tf(s[tn][0]);
            Ps[pr0 * ASTRIDE + col + 1]       = f2tf(s[tn][1]);
            Ps[(pr0 + 8) * ASTRIDE + col]     = f2tf(s[tn][2]);
            Ps[(pr0 + 8) * ASTRIDE + col + 1] = f2tf(s[tn][3]);
        }
        __syncwarp();

        // ---- O += P V ----
        #pragma unroll
        for (int ks = 0; ks < 8; ks++) {
            const int cc = ks * 8 + qd;
            uint32_t a[4];
            a[0] = Ps[pr0 * ASTRIDE + cc];       a[1] = Ps[(pr0 + 8) * ASTRIDE + cc];
            a[2] = Ps[pr0 * ASTRIDE + cc + 4];   a[3] = Ps[(pr0 + 8) * ASTRIDE + cc + 4];
            #pragma unroll
            for (int tn = 0; tn < 8; tn++) {
                uint32_t bb[2];
                bb[0] = Vs[(ks * 8 + qd) * ASTRIDE + tn * 8 + rl];
                bb[1] = Vs[(ks * 8 + qd + 4) * ASTRIDE + tn * 8 + rl];
                mma_tf32(o[tn], a, bb);
            }
        }
        __syncwarp();
    }

    // ---- epilogue: O / l, write as [B, N, H*dh] ----
    const float inv0 = 1.f / l0, inv1 = 1.f / l1;
    const int grow0 = row0g + warp * 16 + rl;
    float* ob = attn_out + ((size_t)(b * SEQ + grow0)) * 1024 + h * 64;
    #pragma unroll
    for (int tn = 0; tn < 8; tn++) {
        int col = tn * 8 + (qd << 1);
        *(float2*)&ob[col] = make_float2(o[tn][0] * inv0, o[tn][1] * inv0);
        *(float2*)&ob[(size_t)8 * 1024 + col] = make_float2(o[tn][2] * inv1, o[tn][3] * inv1);
    }
}

// ============================================================================
// Launch
// ============================================================================
extern "C" void kernel_launch(void* const* d_in, const int* in_sizes, int n_in,
                              void* d_out, int out_size)
{
    const float* x     = (const float*)d_in[0];
    const float* bias  = (const float*)d_in[1];
    const float* Wqkv  = (const float*)d_in[2];
    const float* Wproj = (const float*)d_in[3];
    const float* beta  = (const float*)d_in[4];
    float* out = (float*)d_out;

    float *qkv_ptr = nullptr, *att_ptr = nullptr;
    cudaGetSymbolAddress((void**)&qkv_ptr, g_qkv);
    cudaGetSymbolAddress((void**)&att_ptr, g_att);

    cudaFuncSetAttribute(attn_kernel,
                         cudaFuncAttributeMaxDynamicSharedMemorySize, ATT_SMEM);

    // 1) qkv = x @ Wqkv^T   [8192, 3072]
    gemm_tf32_kernel<<<dim3(MTOK / GBM, 3 * DMODEL / GBN), 256>>>(x, Wqkv, qkv_ptr, 3 * DMODEL);

    // 2) fused attention -> [B, N, H*dh]
    attn_kernel<<<dim3(SEQ / 64, NHEADS, B_SZ), 128, ATT_SMEM>>>(qkv_ptr, bias, beta, att_ptr);

    // 3) out = attn @ Wproj^T   [8192, 1024]
    gemm_tf32_kernel<<<dim3(MTOK / GBM, DMODEL / GBN), 256>>>(att_ptr, Wproj, out, DMODEL);
}

// round 2
// speedup vs baseline: 1.2241x; 1.2241x over previous
#include <cuda_runtime.h>
#include <cstdint>
#include <cstddef>

#define B_SZ   4
#define SEQ    2048
#define DMODEL 1024
#define NPHYS  8
#define MTOK   (B_SZ * SEQ)      // 8192

// Scratch (allocation-free rule: __device__ globals)
__device__ float g_qkv[(size_t)MTOK * 3 * DMODEL];   // [B*N, 3072]
__device__ float g_att[(size_t)MTOK * DMODEL];       // [B*N, 1024]

__device__ __forceinline__ uint32_t f2tf(float x) {
    uint32_t y;
    asm("cvt.rna.tf32.f32 %0, %1;" : "=r"(y) : "f"(x));
    return y;
}

__device__ __forceinline__ void mma_tf32(float* c, const uint32_t* a, const uint32_t* b) {
    asm volatile(
        "mma.sync.aligned.m16n8k8.row.col.f32.tf32.tf32.f32 "
        "{%0,%1,%2,%3}, {%4,%5,%6,%7}, {%8,%9}, {%0,%1,%2,%3};\n"
        : "+f"(c[0]), "+f"(c[1]), "+f"(c[2]), "+f"(c[3])
        : "r"(a[0]), "r"(a[1]), "r"(a[2]), "r"(a[3]), "r"(b[0]), "r"(b[1]));
}

// ============================================================================
// GEMM: C[M, Nout] = A[M, 1024] @ W[Nout, 1024]^T
// Block 128x128, 8 warps (4m x 2n), warp tile 32x64, BK=32.
// Double-buffered SMEM + register-staged global prefetch.
// ============================================================================
#define GBM 128
#define GBN 128
#define GBK 32
#define GST 36
#define GEMM_SMEM (2 * (GBM + GBN) * GST * 4)   // 73728 B

__global__ __launch_bounds__(256) void gemm_tf32_kernel(
    const float* __restrict__ A, const float* __restrict__ W,
    float* __restrict__ C, int Nout)
{
    extern __shared__ uint32_t sm[];
    uint32_t* Asm = sm;                       // [2][GBM*GST]
    uint32_t* Wsm = sm + 2 * GBM * GST;       // [2][GBN*GST]

    const int tid  = threadIdx.x;
    const int lane = tid & 31;
    const int warp = tid >> 5;
    const int wm   = warp & 3;       // 0..3  -> 32 rows each
    const int wn   = warp >> 2;      // 0..1  -> 64 cols each
    const int bm   = blockIdx.x * GBM;
    const int bn   = blockIdx.y * GBN;
    const int rl   = lane >> 2;      // 0..7
    const int qd   = lane & 3;       // 0..3

    const int r8 = tid >> 3;          // load row base (stride 32 per i)
    const int c4 = (tid & 7) << 2;    // load col base

    float c[2][8][4];
    #pragma unroll
    for (int i = 0; i < 2; i++)
        #pragma unroll
        for (int j = 0; j < 8; j++)
            #pragma unroll
            for (int k = 0; k < 4; k++) c[i][j][k] = 0.f;

    float4 ra[4], rw[4];

    // ---- prologue: tile 0 -> regs -> smem[0]; tile 1 -> regs ----
    #pragma unroll
    for (int i = 0; i < 4; i++) {
        ra[i] = *(const float4*)&A[(size_t)(bm + r8 + i * 32) * DMODEL + c4];
        rw[i] = *(const float4*)&W[(size_t)(bn + r8 + i * 32) * DMODEL + c4];
    }
    #pragma unroll
    for (int i = 0; i < 4; i++) {
        uint4 ta = make_uint4(f2tf(ra[i].x), f2tf(ra[i].y), f2tf(ra[i].z), f2tf(ra[i].w));
        uint4 tw = make_uint4(f2tf(rw[i].x), f2tf(rw[i].y), f2tf(rw[i].z), f2tf(rw[i].w));
        *(uint4*)&Asm[(r8 + i * 32) * GST + c4] = ta;
        *(uint4*)&Wsm[(r8 + i * 32) * GST + c4] = tw;
    }
    #pragma unroll
    for (int i = 0; i < 4; i++) {
        ra[i] = *(const float4*)&A[(size_t)(bm + r8 + i * 32) * DMODEL + GBK + c4];
        rw[i] = *(const float4*)&W[(size_t)(bn + r8 + i * 32) * DMODEL + GBK + c4];
    }
    __syncthreads();

    const int NK = DMODEL / GBK;   // 32 stages
    for (int kt = 0; kt < NK; kt++) {
        const int cur = kt & 1;

        if (kt < NK - 1) {
            // regs hold tile kt+1 -> store to smem[cur^1]
            uint32_t* Ad = Asm + (cur ^ 1) * GBM * GST;
            uint32_t* Wd = Wsm + (cur ^ 1) * GBN * GST;
            #pragma unroll
            for (int i = 0; i < 4; i++) {
                uint4 ta = make_uint4(f2tf(ra[i].x), f2tf(ra[i].y), f2tf(ra[i].z), f2tf(ra[i].w));
                uint4 tw = make_uint4(f2tf(rw[i].x), f2tf(rw[i].y), f2tf(rw[i].z), f2tf(rw[i].w));
                *(uint4*)&Ad[(r8 + i * 32) * GST + c4] = ta;
                *(uint4*)&Wd[(r8 + i * 32) * GST + c4] = tw;
            }
        }
        if (kt < NK - 2) {
            const int k0 = (kt + 2) * GBK;
            #pragma unroll
            for (int i = 0; i < 4; i++) {
                ra[i] = *(const float4*)&A[(size_t)(bm + r8 + i * 32) * DMODEL + k0 + c4];
                rw[i] = *(const float4*)&W[(size_t)(bn + r8 + i * 32) * DMODEL + k0 + c4];
            }
        }

        // ---- compute from smem[cur] ----
        const uint32_t* Ab = Asm + cur * GBM * GST;
        const uint32_t* Wb = Wsm + cur * GBN * GST;

        uint32_t aa[2][4][4];
        #pragma unroll
        for (int tm = 0; tm < 2; tm++) {
            const uint32_t* p0 = Ab + (wm * 32 + tm * 16 + rl) * GST;
            const uint32_t* p1 = p0 + 8 * GST;
            #pragma unroll
            for (int ks = 0; ks < 4; ks++) {
                aa[tm][ks][0] = p0[ks * 8 + qd];
                aa[tm][ks][1] = p1[ks * 8 + qd];
                aa[tm][ks][2] = p0[ks * 8 + qd + 4];
                aa[tm][ks][3] = p1[ks * 8 + qd + 4];
            }
        }
        #pragma unroll
        for (int tn = 0; tn < 8; tn++) {
            const uint32_t* bp = Wb + (wn * 64 + tn * 8 + rl) * GST;
            #pragma unroll
            for (int ks = 0; ks < 4; ks++) {
                uint32_t bb[2];
                bb[0] = bp[ks * 8 + qd];
                bb[1] = bp[ks * 8 + qd + 4];
                mma_tf32(c[0][tn], aa[0][ks], bb);
                mma_tf32(c[1][tn], aa[1][ks], bb);
            }
        }
        __syncthreads();
    }

    // ---- epilogue ----
    #pragma unroll
    for (int tm = 0; tm < 2; tm++) {
        int r0 = bm + wm * 32 + tm * 16 + rl;
        #pragma unroll
        for (int tn = 0; tn < 8; tn++) {
            int col = bn + wn * 64 + tn * 8 + (qd << 1);
            *(float2*)&C[(size_t)r0 * Nout + col]       = make_float2(c[tm][tn][0], c[tm][tn][1]);
            *(float2*)&C[(size_t)(r0 + 8) * Nout + col] = make_float2(c[tm][tn][2], c[tm][tn][3]);
        }
    }
}

// ============================================================================
// Fused flash attention. Block = (b, h, 128 query rows). 128 threads, 4 warps.
// Warp w owns rows [w*32, w*32+32)  (two 16-row m-subtiles). Bc = 64, dh = 64.
// ============================================================================
#define AST 68
#define ATT_SMEM ((128 + 64 + 64 + 128) * AST * 4)   // 104448 B

__global__ __launch_bounds__(128) void attn_kernel(
    const float* __restrict__ qkv, const float* __restrict__ bias,
    const float* __restrict__ beta, float* __restrict__ attn_out)
{
    extern __shared__ uint32_t smx[];
    uint32_t* Qs = smx;                         // 128 x AST
    uint32_t* Ks = Qs + 128 * AST;              // 64 x AST
    uint32_t* Vs = Ks + 64 * AST;               // 64 x AST
    uint32_t* Ps = Vs + 64 * AST;               // 128 x AST

    const int tid  = threadIdx.x;
    const int lane = tid & 31;
    const int warp = tid >> 5;      // 0..3
    const int rl   = lane >> 2;     // 0..7
    const int qd   = lane & 3;      // 0..3
    const int h    = blockIdx.y;
    const int b    = blockIdx.z;
    const int row0g = blockIdx.x * 128;

    const bool usebias = (h < NPHYS);
    const float betah  = usebias ? beta[h] : 0.f;
    const float scale  = 0.125f;   // 1/sqrt(64)

    // ---- Load Q tile (128x64) once: 2048 float4, 16 per thread ----
    const float* qbase = qkv + ((size_t)(b * SEQ + row0g)) * 3072 + h * 64;
    #pragma unroll
    for (int i = 0; i < 16; i++) {
        int idx = tid + i * 128;
        int r = idx >> 4, cc4 = (idx & 15) << 2;
        float4 v = *(const float4*)&qbase[(size_t)r * 3072 + cc4];
        *(uint4*)&Qs[r * AST + cc4] = make_uint4(f2tf(v.x), f2tf(v.y), f2tf(v.z), f2tf(v.w));
    }

    float o[2][8][4];
    #pragma unroll
    for (int tm = 0; tm < 2; tm++)
        #pragma unroll
        for (int tn = 0; tn < 8; tn++)
            #pragma unroll
            for (int i = 0; i < 4; i++) o[tm][tn][i] = 0.f;
    float m[2][2] = {{-1e30f, -1e30f}, {-1e30f, -1e30f}};
    float l[2][2] = {{0.f, 0.f}, {0.f, 0.f}};

    for (int jt = 0; jt < 32; jt++) {
        __syncthreads();   // Q stores visible (jt=0); prior K/V reads done (jt>0)

        const float* kb = qkv + ((size_t)(b * SEQ + jt * 64)) * 3072 + 1024 + h * 64;
        const float* vb = kb + 1024;
        #pragma unroll
        for (int i = 0; i < 8; i++) {
            int idx = tid + i * 128;
            int r = idx >> 4, cc4 = (idx & 15) << 2;
            float4 kv = *(const float4*)&kb[(size_t)r * 3072 + cc4];
            *(uint4*)&Ks[r * AST + cc4] = make_uint4(f2tf(kv.x), f2tf(kv.y), f2tf(kv.z), f2tf(kv.w));
            float4 vv = *(const float4*)&vb[(size_t)r * 3072 + cc4];
            *(uint4*)&Vs[r * AST + cc4] = make_uint4(f2tf(vv.x), f2tf(vv.y), f2tf(vv.z), f2tf(vv.w));
        }
        __syncthreads();

        // ---- S = Q K^T  (warp tile 32x64) ----
        float s[2][8][4];
        #pragma unroll
        for (int tm = 0; tm < 2; tm++)
            #pragma unroll
            for (int tn = 0; tn < 8; tn++)
                #pragma unroll
                for (int i = 0; i < 4; i++) s[tm][tn][i] = 0.f;

        #pragma unroll
        for (int ks = 0; ks < 8; ks++) {
            const int cc = ks * 8 + qd;
            uint32_t a0[4], a1[4];
            {
                int r0 = warp * 32 + rl;
                a0[0] = Qs[r0 * AST + cc];        a0[1] = Qs[(r0 + 8) * AST + cc];
                a0[2] = Qs[r0 * AST + cc + 4];    a0[3] = Qs[(r0 + 8) * AST + cc + 4];
                int r1 = r0 + 16;
                a1[0] = Qs[r1 * AST + cc];        a1[1] = Qs[(r1 + 8) * AST + cc];
                a1[2] = Qs[r1 * AST + cc + 4];    a1[3] = Qs[(r1 + 8) * AST + cc + 4];
            }
            #pragma unroll
            for (int tn = 0; tn < 8; tn++) {
                uint32_t bb[2];
                const uint32_t* kp = Ks + (tn * 8 + rl) * AST;
                bb[0] = kp[cc]; bb[1] = kp[cc + 4];
                mma_tf32(s[0][tn], a0, bb);
                mma_tf32(s[1][tn], a1, bb);
            }
        }

        // ---- scale + bias ----
        #pragma unroll
        for (int tm = 0; tm < 2; tm++) {
            if (usebias) {
                int grow = row0g + warp * 32 + tm * 16 + rl;
                const float* bb0 = bias + ((size_t)b * SEQ + grow) * SEQ + jt * 64;
                const float* bb1 = bb0 + (size_t)8 * SEQ;
                #pragma unroll
                for (int tn = 0; tn < 8; tn++) {
                    int col = tn * 8 + (qd << 1);
                    float2 x0 = *(const float2*)&bb0[col];
                    float2 x1 = *(const float2*)&bb1[col];
                    s[tm][tn][0] = s[tm][tn][0] * scale + betah * x0.x;
                    s[tm][tn][1] = s[tm][tn][1] * scale + betah * x0.y;
                    s[tm][tn][2] = s[tm][tn][2] * scale + betah * x1.x;
                    s[tm][tn][3] = s[tm][tn][3] * scale + betah * x1.y;
                }
            } else {
                #pragma unroll
                for (int tn = 0; tn < 8; tn++)
                    #pragma unroll
                    for (int i = 0; i < 4; i++) s[tm][tn][i] *= scale;
            }
        }

        // ---- online softmax ----
        #pragma unroll
        for (int tm = 0; tm < 2; tm++) {
            float mx0 = -1e30f, mx1 = -1e30f;
            #pragma unroll
            for (int tn = 0; tn < 8; tn++) {
                mx0 = fmaxf(mx0, fmaxf(s[tm][tn][0], s[tm][tn][1]));
                mx1 = fmaxf(mx1, fmaxf(s[tm][tn][2], s[tm][tn][3]));
            }
            mx0 = fmaxf(mx0, __shfl_xor_sync(0xffffffffu, mx0, 1));
            mx0 = fmaxf(mx0, __shfl_xor_sync(0xffffffffu, mx0, 2));
            mx1 = fmaxf(mx1, __shfl_xor_sync(0xffffffffu, mx1, 1));
            mx1 = fmaxf(mx1, __shfl_xor_sync(0xffffffffu, mx1, 2));

            float mn0 = fmaxf(m[tm][0], mx0), mn1 = fmaxf(m[tm][1], mx1);
            float f0 = __expf(m[tm][0] - mn0), f1 = __expf(m[tm][1] - mn1);
            float sum0 = 0.f, sum1 = 0.f;
            #pragma unroll
            for (int tn = 0; tn < 8; tn++) {
                s[tm][tn][0] = __expf(s[tm][tn][0] - mn0);
                s[tm][tn][1] = __expf(s[tm][tn][1] - mn0);
                s[tm][tn][2] = __expf(s[tm][tn][2] - mn1);
                s[tm][tn][3] = __expf(s[tm][tn][3] - mn1);
                sum0 += s[tm][tn][0] + s[tm][tn][1];
                sum1 += s[tm][tn][2] + s[tm][tn][3];
            }
            sum0 += __shfl_xor_sync(0xffffffffu, sum0, 1);
            sum0 += __shfl_xor_sync(0xffffffffu, sum0, 2);
            sum1 += __shfl_xor_sync(0xffffffffu, sum1, 1);
            sum1 += __shfl_xor_sync(0xffffffffu, sum1, 2);
            l[tm][0] = l[tm][0] * f0 + sum0;
            l[tm][1] = l[tm][1] * f1 + sum1;
            m[tm][0] = mn0; m[tm][1] = mn1;
            #pragma unroll
            for (int tn = 0; tn < 8; tn++) {
                o[tm][tn][0] *= f0; o[tm][tn][1] *= f0;
                o[tm][tn][2] *= f1; o[tm][tn][3] *= f1;
            }
        }

        // ---- stage P (C-frag -> SMEM, warp-private rows) ----
        #pragma unroll
        for (int tm = 0; tm < 2; tm++) {
            int pr = warp * 32 + tm * 16 + rl;
            #pragma unroll
            for (int tn = 0; tn < 8; tn++) {
                int col = tn * 8 + (qd << 1);
                Ps[pr * AST + col]           = f2tf(s[tm][tn][0]);
                Ps[pr * AST + col + 1]       = f2tf(s[tm][tn][1]);
                Ps[(pr + 8) * AST + col]     = f2tf(s[tm][tn][2]);
                Ps[(pr + 8) * AST + col + 1] = f2tf(s[tm][tn][3]);
            }
        }
        __syncwarp();

        // ---- O += P V ----
        #pragma unroll
        for (int ks = 0; ks < 8; ks++) {
            const int cc = ks * 8 + qd;
            uint32_t a0[4], a1[4];
            {
                int r0 = warp * 32 + rl;
                a0[0] = Ps[r0 * AST + cc];        a0[1] = Ps[(r0 + 8) * AST + cc];
                a0[2] = Ps[r0 * AST + cc + 4];    a0[3] = Ps[(r0 + 8) * AST + cc + 4];
                int r1 = r0 + 16;
                a1[0] = Ps[r1 * AST + cc];        a1[1] = Ps[(r1 + 8) * AST + cc];
                a1[2] = Ps[r1 * AST + cc + 4];    a1[3] = Ps[(r1 + 8) * AST + cc + 4];
            }
            #pragma unroll
            for (int tn = 0; tn < 8; tn++) {
                uint32_t bb[2];
                bb[0] = Vs[cc * AST + tn * 8 + rl];
                bb[1] = Vs[(cc + 4) * AST + tn * 8 + rl];
                mma_tf32(o[0][tn], a0, bb);
                mma_tf32(o[1][tn], a1, bb);
            }
        }
    }

    // ---- epilogue: O / l -> attn_out [B, N, H*dh] ----
    #pragma unroll
    for (int tm = 0; tm < 2; tm++) {
        float inv0 = 1.f / l[tm][0], inv1 = 1.f / l[tm][1];
        int grow = row0g + warp * 32 + tm * 16 + rl;
        float* ob = attn_out + ((size_t)(b * SEQ + grow)) * 1024 + h * 64;
        #pragma unroll
        for (int tn = 0; tn < 8; tn++) {
            int col = tn * 8 + (qd << 1);
            *(float2*)&ob[col] = make_float2(o[tm][tn][0] * inv0, o[tm][tn][1] * inv0);
            *(float2*)&ob[(size_t)8 * 1024 + col] = make_float2(o[tm][tn][2] * inv1, o[tm][tn][3] * inv1);
        }
    }
}

// ============================================================================
// Launch
// ============================================================================
extern "C" void kernel_launch(void* const* d_in, const int* in_sizes, int n_in,
                              void* d_out, int out_size)
{
    const float* x     = (const float*)d_in[0];
    const float* bias  = (const float*)d_in[1];
    const float* Wqkv  = (const float*)d_in[2];
    const float* Wproj = (const float*)d_in[3];
    const float* beta  = (const float*)d_in[4];
    float* out = (float*)d_out;

    float *qkv_ptr = nullptr, *att_ptr = nullptr;
    cudaGetSymbolAddress((void**)&qkv_ptr, g_qkv);
    cudaGetSymbolAddress((void**)&att_ptr, g_att);

    cudaFuncSetAttribute(gemm_tf32_kernel,
                         cudaFuncAttributeMaxDynamicSharedMemorySize, GEMM_SMEM);
    cudaFuncSetAttribute(attn_kernel,
                         cudaFuncAttributeMaxDynamicSharedMemorySize, ATT_SMEM);

    // 1) qkv = x @ Wqkv^T   [8192, 3072]
    gemm_tf32_kernel<<<dim3(MTOK / GBM, 3 * DMODEL / GBN), 256, GEMM_SMEM>>>(
        x, Wqkv, qkv_ptr, 3 * DMODEL);

    // 2) fused attention -> [B, N, H*dh]
    attn_kernel<<<dim3(SEQ / 128, 16, B_SZ), 128, ATT_SMEM>>>(qkv_ptr, bias, beta, att_ptr);

    // 3) out = attn @ Wproj^T   [8192, 1024]
    gemm_tf32_kernel<<<dim3(MTOK / GBM, DMODEL / GBN), 256, GEMM_SMEM>>>(
        att_ptr, Wproj, out, DMODEL);
}

// round 4
// speedup vs baseline: 1.3938x; 1.1387x over previous
#include <cuda_runtime.h>
#include <cstdint>
#include <cstddef>

#define B_SZ   4
#define SEQ    2048
#define DMODEL 1024
#define NPHYS  8
#define MTOK   (B_SZ * SEQ)      // 8192

// Scratch (allocation-free rule: __device__ globals)
__device__ float g_qkv[(size_t)MTOK * 3 * DMODEL];   // [B*N, 3072]
__device__ float g_att[(size_t)MTOK * DMODEL];       // [B*N, 1024]
__device__ float g_xr[(size_t)MTOK * DMODEL];        // tf32-rounded x
__device__ float g_wqkvr[(size_t)3 * DMODEL * DMODEL];
__device__ float g_wprojr[(size_t)DMODEL * DMODEL];

__device__ __forceinline__ uint32_t f2tf(float x) {
    uint32_t y;
    asm("cvt.rna.tf32.f32 %0, %1;" : "=r"(y) : "f"(x));
    return y;
}

__device__ __forceinline__ uint32_t smem_u32(const void* p) {
    uint32_t a;
    asm("{ .reg .u64 t; cvta.to.shared.u64 t, %1; cvt.u32.u64 %0, t; }" : "=r"(a) : "l"(p));
    return a;
}

__device__ __forceinline__ void mma_tf32(float* c, const uint32_t* a, const uint32_t* b) {
    asm volatile(
        "mma.sync.aligned.m16n8k8.row.col.f32.tf32.tf32.f32 "
        "{%0,%1,%2,%3}, {%4,%5,%6,%7}, {%8,%9}, {%0,%1,%2,%3};\n"
        : "+f"(c[0]), "+f"(c[1]), "+f"(c[2]), "+f"(c[3])
        : "r"(a[0]), "r"(a[1]), "r"(a[2]), "r"(a[3]), "r"(b[0]), "r"(b[1]));
}

__device__ __forceinline__ void cp16(uint32_t dst, const float* src) {
    asm volatile("cp.async.cg.shared.global [%0], [%1], 16;" :: "r"(dst), "l"(src));
}
#define CP_COMMIT() asm volatile("cp.async.commit_group;" ::: "memory")
#define CP_WAIT1()  asm volatile("cp.async.wait_group 1;" ::: "memory")
#define CP_WAIT2()  asm volatile("cp.async.wait_group 2;" ::: "memory")

// ============================================================================
// Pre-round to tf32 (RNA): GEMM operands then need no cvt (HW sees tf32 bits).
// ============================================================================
__global__ void round_tf32_kernel(const float* __restrict__ in,
                                  float* __restrict__ out, int n4)
{
    int i = blockIdx.x * blockDim.x + threadIdx.x;
    if (i >= n4) return;
    float4 v = ((const float4*)in)[i];
    float4 r;
    r.x = __uint_as_float(f2tf(v.x)); r.y = __uint_as_float(f2tf(v.y));
    r.z = __uint_as_float(f2tf(v.z)); r.w = __uint_as_float(f2tf(v.w));
    ((float4*)out)[i] = r;
}

// ============================================================================
// GEMM: C[M, Nout] = A[M, 1024] @ W[Nout, 1024]^T
// Block 128x128, 4 warps (2m x 2n), warp tile 64x64, BK=32.
// 3-stage cp.async pipeline of raw (pre-rounded) fp32, XOR-swizzled smem.
// ============================================================================
#define GNSTG 3
#define GSTGB 32768          // per stage: A 16KB + B 16KB
#define GEMM_SMEM (GNSTG * GSTGB)   // 98304

__global__ __launch_bounds__(128) void gemm_ws_kernel(
    const float* __restrict__ A, const float* __restrict__ W,
    float* __restrict__ C, int Nout)
{
    extern __shared__ uint32_t gsm[];
    const uint32_t sb = smem_u32(gsm);
    const int tid  = threadIdx.x;
    const int lane = tid & 31;
    const int warp = tid >> 5;
    const int wm   = warp & 1;       // 2 x 64 rows
    const int wn   = warp >> 1;      // 2 x 64 cols
    const int rl   = lane >> 2;      // 0..7
    const int qd   = lane & 3;       // 0..3
    const size_t bm = (size_t)blockIdx.x * 128;
    const size_t bn = (size_t)blockIdx.y * 128;

    float c[4][8][4];
    #pragma unroll
    for (int i = 0; i < 4; i++)
        #pragma unroll
        for (int j = 0; j < 8; j++)
            #pragma unroll
            for (int k = 0; k < 4; k++) c[i][j][k] = 0.f;

    auto load_stage = [&](int chunk, int buf) {
        const uint32_t baseA = sb + buf * GSTGB;
        const uint32_t baseB = baseA + 16384;
        #pragma unroll
        for (int i = 0; i < 8; i++) {
            int idx = tid + i * 128;
            int row = idx >> 3, c16 = idx & 7;
            int sw = (c16 * 4) ^ ((row & 7) << 2);
            cp16(baseA + row * 128 + sw * 4, A + (bm + row) * DMODEL + chunk * 32 + c16 * 4);
        }
        #pragma unroll
        for (int i = 0; i < 8; i++) {
            int idx = tid + i * 128;
            int row = idx >> 3, c16 = idx & 7;
            int sw = (c16 * 4) ^ ((row & 7) << 2);
            cp16(baseB + row * 128 + sw * 4, W + (bn + row) * DMODEL + chunk * 32 + c16 * 4);
        }
    };

    load_stage(0, 0); CP_COMMIT();
    load_stage(1, 1); CP_COMMIT();

    const int NCHUNK = DMODEL / 32;   // 32
    for (int kt = 0; kt < NCHUNK; kt++) {
        CP_WAIT1();          // stage kt complete (kt+1 may pend)
        __syncthreads();     // visible to all; prior compute on target buf done
        if (kt + 2 < NCHUNK) load_stage(kt + 2, (kt + 2) % GNSTG);
        CP_COMMIT();

        const uint32_t* As = gsm + (kt % GNSTG) * (GSTGB / 4);
        const uint32_t* Bs = As + 4096;

        #pragma unroll
        for (int ks = 0; ks < 4; ks++) {
            const int cc = ks * 8 + qd;
            uint32_t a[4][4];
            #pragma unroll
            for (int tm = 0; tm < 4; tm++) {
                int r0 = wm * 64 + tm * 16 + rl;
                int x0 = cc ^ ((r0 & 7) << 2);
                int x1 = (cc + 4) ^ ((r0 & 7) << 2);
                const uint32_t* p0 = As + r0 * 32;
                const uint32_t* p1 = p0 + 8 * 32;
                a[tm][0] = p0[x0]; a[tm][1] = p1[x0];
                a[tm][2] = p0[x1]; a[tm][3] = p1[x1];
            }
            #pragma unroll
            for (int tn = 0; tn < 8; tn++) {
                int r = wn * 64 + tn * 8 + rl;
                int x0 = cc ^ ((r & 7) << 2);
                int x1 = (cc + 4) ^ ((r & 7) << 2);
                uint32_t b[2] = { Bs[r * 32 + x0], Bs[r * 32 + x1] };
                #pragma unroll
                for (int tm = 0; tm < 4; tm++)
                    mma_tf32(c[tm][tn], a[tm], b);
            }
        }
    }

    // ---- epilogue ----
    #pragma unroll
    for (int tm = 0; tm < 4; tm++) {
        size_t r0 = bm + wm * 64 + tm * 16 + rl;
        #pragma unroll
        for (int tn = 0; tn < 8; tn++) {
            int col = (int)bn + wn * 64 + tn * 8 + (qd << 1);
            *(float2*)&C[r0 * Nout + col]       = make_float2(c[tm][tn][0], c[tm][tn][1]);
            *(float2*)&C[(r0 + 8) * Nout + col] = make_float2(c[tm][tn][2], c[tm][tn][3]);
        }
    }
}

// ============================================================================
// Fused flash attention. Block = (b, h, 128 query rows). 128 threads, 4 warps.
// Warp w owns 32 rows. Bc = 64, dh = 64. K double-buffered + V single via
// cp.async (raw fp32, cvt.rna at fragment load). XOR-swizzled smem.
// SMEM words: Q[0,8192) K0[8192,12288) K1[12288,16384) V[16384,20480) P[20480,28672)
// ============================================================================
#define ATT_SMEM (28672 * 4)   // 114688 B

__global__ __launch_bounds__(128) void attn_kernel(
    const float* __restrict__ qkv, const float* __restrict__ bias,
    const float* __restrict__ beta, float* __restrict__ attn_out)
{
    extern __shared__ uint32_t smx[];
    uint32_t* Qs = smx;                 // converted tf32 bits
    uint32_t* Ps = smx + 20480;         // converted tf32 bits
    const uint32_t sb = smem_u32(smx);
    const uint32_t kAddr[2] = { sb + 8192 * 4, sb + 12288 * 4 };
    const uint32_t vAddr = sb + 16384 * 4;

    const int tid  = threadIdx.x;
    const int lane = tid & 31;
    const int warp = tid >> 5;
    const int rl   = lane >> 2;
    const int qd   = lane & 3;
    const int h    = blockIdx.y;
    const int b    = blockIdx.z;
    const int row0g = blockIdx.x * 128;

    const bool usebias = (h < NPHYS);
    const float betah  = usebias ? beta[h] : 0.f;
    const float scale  = 0.125f;

    const float* kvbase = qkv + (size_t)b * SEQ * 3072 + h * 64;

    // K/V tile loader: 64 rows x 64 words; 1024 16B-chunks; 8 per thread.
    auto load_kv = [&](const float* src, uint32_t dstBase, int shift) {
        #pragma unroll
        for (int i = 0; i < 8; i++) {
            int idx = tid + i * 128;
            int row = idx >> 4, c16 = idx & 15;
            int sw = (c16 * 4) ^ ((row & 7) << shift);
            cp16(dstBase + (row * 64 + sw) * 4, src + (size_t)row * 3072 + c16 * 4);
        }
    };

    // prologue: K(0)
    load_kv(kvbase + 1024, kAddr[0], 2); CP_COMMIT();

    // Q tile (128 x 64) converted: 2048 float4, 16 per thread
    const float* qbase = qkv + ((size_t)(b * SEQ + row0g)) * 3072 + h * 64;
    #pragma unroll
    for (int i = 0; i < 16; i++) {
        int idx = tid + i * 128;
        int row = idx >> 4, c16 = idx & 15;
        float4 v = *(const float4*)&qbase[(size_t)row * 3072 + c16 * 4];
        int sw = (c16 * 4) ^ ((row & 7) << 2);
        *(uint4*)&Qs[row * 64 + sw] = make_uint4(f2tf(v.x), f2tf(v.y), f2tf(v.z), f2tf(v.w));
    }

    float o[2][8][4];
    #pragma unroll
    for (int tm = 0; tm < 2; tm++)
        #pragma unroll
        for (int tn = 0; tn < 8; tn++)
            #pragma unroll
            for (int i = 0; i < 4; i++) o[tm][tn][i] = 0.f;
    float m[2][2] = {{-1e30f, -1e30f}, {-1e30f, -1e30f}};
    float l[2][2] = {{0.f, 0.f}, {0.f, 0.f}};

    for (int jt = 0; jt < 32; jt++) {
        __syncthreads();   // prev PV reads of V/Ps and QK reads of K[(jt+1)&1] done; Q visible at jt=0

        // issue V(jt), then K(jt+1)
        load_kv(kvbase + (size_t)jt * 64 * 3072 + 2048, vAddr, 3); CP_COMMIT();
        if (jt + 1 < 32) load_kv(kvbase + (size_t)(jt + 1) * 64 * 3072 + 1024, kAddr[(jt + 1) & 1], 2);
        CP_COMMIT();

        CP_WAIT2();        // K(jt) complete
        __syncthreads();

        const uint32_t* Ks = smx + 8192 + (jt & 1) * 4096;

        // ---- S = Q K^T (warp tile 32x64) ----
        float s[2][8][4];
        #pragma unroll
        for (int tm = 0; tm < 2; tm++)
            #pragma unroll
            for (int tn = 0; tn < 8; tn++)
                #pragma unroll
                for (int i = 0; i < 4; i++) s[tm][tn][i] = 0.f;

        #pragma unroll
        for (int ks = 0; ks < 8; ks++) {
            const int cc = ks * 8 + qd;
            const int xq0 = cc ^ (rl << 2), xq1 = (cc + 4) ^ (rl << 2);
            uint32_t a0[4], a1[4];
            {
                int r0 = warp * 32 + rl;
                a0[0] = Qs[r0 * 64 + xq0];        a0[1] = Qs[(r0 + 8) * 64 + xq0];
                a0[2] = Qs[r0 * 64 + xq1];        a0[3] = Qs[(r0 + 8) * 64 + xq1];
                a1[0] = Qs[(r0 + 16) * 64 + xq0]; a1[1] = Qs[(r0 + 24) * 64 + xq0];
                a1[2] = Qs[(r0 + 16) * 64 + xq1]; a1[3] = Qs[(r0 + 24) * 64 + xq1];
            }
            #pragma unroll
            for (int tn = 0; tn < 8; tn++) {
                int kr = tn * 8 + rl;
                uint32_t bb[2];
                bb[0] = f2tf(__uint_as_float(Ks[kr * 64 + xq0]));
                bb[1] = f2tf(__uint_as_float(Ks[kr * 64 + xq1]));
                mma_tf32(s[0][tn], a0, bb);
                mma_tf32(s[1][tn], a1, bb);
            }
        }

        // ---- scale + bias ----
        #pragma unroll
        for (int tm = 0; tm < 2; tm++) {
            if (usebias) {
                int grow = row0g + warp * 32 + tm * 16 + rl;
                const float* bb0 = bias + ((size_t)b * SEQ + grow) * SEQ + jt * 64;
                const float* bb1 = bb0 + (size_t)8 * SEQ;
                #pragma unroll
                for (int tn = 0; tn < 8; tn++) {
                    int col = tn * 8 + (qd << 1);
                    float2 x0 = *(const float2*)&bb0[col];
                    float2 x1 = *(const float2*)&bb1[col];
                    s[tm][tn][0] = s[tm][tn][0] * scale + betah * x0.x;
                    s[tm][tn][1] = s[tm][tn][1] * scale + betah * x0.y;
                    s[tm][tn][2] = s[tm][tn][2] * scale + betah * x1.x;
                    s[tm][tn][3] = s[tm][tn][3] * scale + betah * x1.y;
                }
            } else {
                #pragma unroll
                for (int tn = 0; tn < 8; tn++)
                    #pragma unroll
                    for (int i = 0; i < 4; i++) s[tm][tn][i] *= scale;
            }
        }

        // ---- online softmax ----
        #pragma unroll
        for (int tm = 0; tm < 2; tm++) {
            float mx0 = -1e30f, mx1 = -1e30f;
            #pragma unroll
            for (int tn = 0; tn < 8; tn++) {
                mx0 = fmaxf(mx0, fmaxf(s[tm][tn][0], s[tm][tn][1]));
                mx1 = fmaxf(mx1, fmaxf(s[tm][tn][2], s[tm][tn][3]));
            }
            mx0 = fmaxf(mx0, __shfl_xor_sync(0xffffffffu, mx0, 1));
            mx0 = fmaxf(mx0, __shfl_xor_sync(0xffffffffu, mx0, 2));
            mx1 = fmaxf(mx1, __shfl_xor_sync(0xffffffffu, mx1, 1));
            mx1 = fmaxf(mx1, __shfl_xor_sync(0xffffffffu, mx1, 2));

            float mn0 = fmaxf(m[tm][0], mx0), mn1 = fmaxf(m[tm][1], mx1);
            float f0 = __expf(m[tm][0] - mn0), f1 = __expf(m[tm][1] - mn1);
            float sum0 = 0.f, sum1 = 0.f;
            #pragma unroll
            for (int tn = 0; tn < 8; tn++) {
                s[tm][tn][0] = __expf(s[tm][tn][0] - mn0);
                s[tm][tn][1] = __expf(s[tm][tn][1] - mn0);
                s[tm][tn][2] = __expf(s[tm][tn][2] - mn1);
                s[tm][tn][3] = __expf(s[tm][tn][3] - mn1);
                sum0 += s[tm][tn][0] + s[tm][tn][1];
                sum1 += s[tm][tn][2] + s[tm][tn][3];
            }
            sum0 += __shfl_xor_sync(0xffffffffu, sum0, 1);
            sum0 += __shfl_xor_sync(0xffffffffu, sum0, 2);
            sum1 += __shfl_xor_sync(0xffffffffu, sum1, 1);
            sum1 += __shfl_xor_sync(0xffffffffu, sum1, 2);
            l[tm][0] = l[tm][0] * f0 + sum0;
            l[tm][1] = l[tm][1] * f1 + sum1;
            m[tm][0] = mn0; m[tm][1] = mn1;
            #pragma unroll
            for (int tn = 0; tn < 8; tn++) {
                o[tm][tn][0] *= f0; o[tm][tn][1] *= f0;
                o[tm][tn][2] *= f1; o[tm][tn][3] *= f1;
            }
        }

        // ---- stage P (C-frag -> SMEM, warp-private rows, swizzled) ----
        #pragma unroll
        for (int tm = 0; tm < 2; tm++) {
            int pr = warp * 32 + tm * 16 + rl;
            #pragma unroll
            for (int tn = 0; tn < 8; tn++) {
                int x = (tn * 8 + (qd << 1)) ^ (rl << 2);
                *(uint2*)&Ps[pr * 64 + x]       = make_uint2(f2tf(s[tm][tn][0]), f2tf(s[tm][tn][1]));
                *(uint2*)&Ps[(pr + 8) * 64 + x] = make_uint2(f2tf(s[tm][tn][2]), f2tf(s[tm][tn][3]));
            }
        }
        __syncwarp();

        CP_WAIT1();        // V(jt) complete (K(jt+1) may pend)
        __syncthreads();

        const uint32_t* Vs = smx + 16384;

        // ---- O += P V ----
        #pragma unroll
        for (int ks = 0; ks < 8; ks++) {
            const int cc = ks * 8 + qd;
            const int xp0 = cc ^ (rl << 2), xp1 = (cc + 4) ^ (rl << 2);
            uint32_t a0[4], a1[4];
            {
                int r0 = warp * 32 + rl;
                a0[0] = Ps[r0 * 64 + xp0];        a0[1] = Ps[(r0 + 8) * 64 + xp0];
                a0[2] = Ps[r0 * 64 + xp1];        a0[3] = Ps[(r0 + 8) * 64 + xp1];
                a1[0] = Ps[(r0 + 16) * 64 + xp0]; a1[1] = Ps[(r0 + 24) * 64 + xp0];
                a1[2] = Ps[(r0 + 16) * 64 + xp1]; a1[3] = Ps[(r0 + 24) * 64 + xp1];
            }
            #pragma unroll
            for (int tn = 0; tn < 8; tn++) {
                int dh = tn * 8 + rl;
                uint32_t bb[2];
                bb[0] = f2tf(__uint_as_float(Vs[cc * 64 + (dh ^ (qd << 3))]));
                bb[1] = f2tf(__uint_as_float(Vs[(cc + 4) * 64 + (dh ^ (((qd + 4) & 7) << 3))]));
                mma_tf32(o[0][tn], a0, bb);
                mma_tf32(o[1][tn], a1, bb);
            }
        }
    }

    // ---- epilogue: O / l (tf32-rounded for the raw-fed proj GEMM) ----
    #pragma unroll
    for (int tm = 0; tm < 2; tm++) {
        float inv0 = 1.f / l[tm][0], inv1 = 1.f / l[tm][1];
        int grow = row0g + warp * 32 + tm * 16 + rl;
        float* ob = attn_out + ((size_t)(b * SEQ + grow)) * 1024 + h * 64;
        #pragma unroll
        for (int tn = 0; tn < 8; tn++) {
            int col = tn * 8 + (qd << 1);
            *(float2*)&ob[col] = make_float2(
                __uint_as_float(f2tf(o[tm][tn][0] * inv0)),
                __uint_as_float(f2tf(o[tm][tn][1] * inv0)));
            *(float2*)&ob[(size_t)8 * 1024 + col] = make_float2(
                __uint_as_float(f2tf(o[tm][tn][2] * inv1)),
                __uint_as_float(f2tf(o[tm][tn][3] * inv1)));
        }
    }
}

// ============================================================================
// Launch
// ============================================================================
extern "C" void kernel_launch(void* const* d_in, const int* in_sizes, int n_in,
                              void* d_out, int out_size)
{
    const float* x     = (const float*)d_in[0];
    const float* bias  = (const float*)d_in[1];
    const float* Wqkv  = (const float*)d_in[2];
    const float* Wproj = (const float*)d_in[3];
    const float* beta  = (const float*)d_in[4];
    float* out = (float*)d_out;

    float *qkv_ptr, *att_ptr, *xr, *wqkvr, *wprojr;
    cudaGetSymbolAddress((void**)&qkv_ptr, g_qkv);
    cudaGetSymbolAddress((void**)&att_ptr, g_att);
    cudaGetSymbolAddress((void**)&xr, g_xr);
    cudaGetSymbolAddress((void**)&wqkvr, g_wqkvr);
    cudaGetSymbolAddress((void**)&wprojr, g_wprojr);

    cudaFuncSetAttribute(gemm_ws_kernel,
                         cudaFuncAttributeMaxDynamicSharedMemorySize, GEMM_SMEM);
    cudaFuncSetAttribute(attn_kernel,
                         cudaFuncAttributeMaxDynamicSharedMemorySize, ATT_SMEM);

    // 0) pre-round GEMM operands to tf32 (RNA) — GEMM then feeds raw bits
    {
        int n4;
        n4 = MTOK * DMODEL / 4;
        round_tf32_kernel<<<(n4 + 255) / 256, 256>>>(x, xr, n4);
        n4 = 3 * DMODEL * DMODEL / 4;
        round_tf32_kernel<<<(n4 + 255) / 256, 256>>>(Wqkv, wqkvr, n4);
        n4 = DMODEL * DMODEL / 4;
        round_tf32_kernel<<<(n4 + 255) / 256, 256>>>(Wproj, wprojr, n4);
    }

    // 1) qkv = x @ Wqkv^T   [8192, 3072]
    gemm_ws_kernel<<<dim3(MTOK / 128, 3 * DMODEL / 128), 128, GEMM_SMEM>>>(
        xr, wqkvr, qkv_ptr, 3 * DMODEL);

    // 2) fused attention -> [B, N, H*dh]
    attn_kernel<<<dim3(SEQ / 128, 16, B_SZ), 128, ATT_SMEM>>>(qkv_ptr, bias, beta, att_ptr);

    // 3) out = attn @ Wproj^T   [8192, 1024]
    gemm_ws_kernel<<<dim3(MTOK / 128, DMODEL / 128), 128, GEMM_SMEM>>>(
        att_ptr, wprojr, out, DMODEL);
}

// round 6
// speedup vs baseline: 1.4815x; 1.0628x over previous
#include <cuda_runtime.h>
#include <cstdint>
#include <cstddef>

#define B_SZ   4
#define SEQ    2048
#define DMODEL 1024
#define NPHYS  8
#define MTOK   (B_SZ * SEQ)      // 8192

// Scratch (allocation-free rule: __device__ globals)
__device__ float g_qkv[(size_t)MTOK * 3 * DMODEL];   // [B*N, 3072] (tf32-rounded)
__device__ float g_att[(size_t)MTOK * DMODEL];       // [B*N, 1024] (tf32-rounded)
__device__ float g_xr[(size_t)MTOK * DMODEL];        // tf32-rounded x
__device__ float g_wqkvr[(size_t)3 * DMODEL * DMODEL];
__device__ float g_wprojr[(size_t)DMODEL * DMODEL];

__device__ __forceinline__ uint32_t f2tf(float x) {
    uint32_t y;
    asm("cvt.rna.tf32.f32 %0, %1;" : "=r"(y) : "f"(x));
    return y;
}

__device__ __forceinline__ uint32_t smem_u32(const void* p) {
    uint32_t a;
    asm("{ .reg .u64 t; cvta.to.shared.u64 t, %1; cvt.u32.u64 %0, t; }" : "=r"(a) : "l"(p));
    return a;
}

__device__ __forceinline__ void mma_tf32(float* c, const uint32_t* a, const uint32_t* b) {
    asm volatile(
        "mma.sync.aligned.m16n8k8.row.col.f32.tf32.tf32.f32 "
        "{%0,%1,%2,%3}, {%4,%5,%6,%7}, {%8,%9}, {%0,%1,%2,%3};\n"
        : "+f"(c[0]), "+f"(c[1]), "+f"(c[2]), "+f"(c[3])
        : "r"(a[0]), "r"(a[1]), "r"(a[2]), "r"(a[3]), "r"(b[0]), "r"(b[1]));
}

__device__ __forceinline__ void cp16(uint32_t dst, const float* src) {
    asm volatile("cp.async.cg.shared.global [%0], [%1], 16;" :: "r"(dst), "l"(src));
}
#define CP_COMMIT() asm volatile("cp.async.commit_group;" ::: "memory")
#define CP_WAIT1()  asm volatile("cp.async.wait_group 1;" ::: "memory")
#define CP_WAIT2()  asm volatile("cp.async.wait_group 2;" ::: "memory")

// ============================================================================
// Pre-round to tf32 (RNA): GEMM operands then need no cvt (HW sees tf32 bits).
// ============================================================================
__global__ void round_tf32_kernel(const float* __restrict__ in,
                                  float* __restrict__ out, int n4)
{
    int i = blockIdx.x * blockDim.x + threadIdx.x;
    if (i >= n4) return;
    float4 v = ((const float4*)in)[i];
    float4 r;
    r.x = __uint_as_float(f2tf(v.x)); r.y = __uint_as_float(f2tf(v.y));
    r.z = __uint_as_float(f2tf(v.z)); r.w = __uint_as_float(f2tf(v.w));
    ((float4*)out)[i] = r;
}

// ============================================================================
// GEMM: C[M, Nout] = A[M, 1024] @ W[Nout, 1024]^T
// Block 128x128, 4 warps (2m x 2n), warp tile 64x64, BK=32.
// 3-stage cp.async pipeline of raw (pre-rounded) fp32, XOR-swizzled smem.
// round_out=1: store tf32-rounded values (for GEMM1 -> attention).
// ============================================================================
#define GNSTG 3
#define GSTGB 32768          // per stage: A 16KB + B 16KB
#define GEMM_SMEM (GNSTG * GSTGB)   // 98304

__global__ __launch_bounds__(128) void gemm_ws_kernel(
    const float* __restrict__ A, const float* __restrict__ W,
    float* __restrict__ C, int Nout, int round_out)
{
    extern __shared__ uint32_t gsm[];
    const uint32_t sb = smem_u32(gsm);
    const int tid  = threadIdx.x;
    const int lane = tid & 31;
    const int warp = tid >> 5;
    const int wm   = warp & 1;
    const int wn   = warp >> 1;
    const int rl   = lane >> 2;
    const int qd   = lane & 3;
    const size_t bm = (size_t)blockIdx.x * 128;
    const size_t bn = (size_t)blockIdx.y * 128;

    float c[4][8][4];
    #pragma unroll
    for (int i = 0; i < 4; i++)
        #pragma unroll
        for (int j = 0; j < 8; j++)
            #pragma unroll
            for (int k = 0; k < 4; k++) c[i][j][k] = 0.f;

    auto load_stage = [&](int chunk, int buf) {
        const uint32_t baseA = sb + buf * GSTGB;
        const uint32_t baseB = baseA + 16384;
        #pragma unroll
        for (int i = 0; i < 8; i++) {
            int idx = tid + i * 128;
            int row = idx >> 3, c16 = idx & 7;
            int sw = (c16 * 4) ^ ((row & 7) << 2);
            cp16(baseA + row * 128 + sw * 4, A + (bm + row) * DMODEL + chunk * 32 + c16 * 4);
        }
        #pragma unroll
        for (int i = 0; i < 8; i++) {
            int idx = tid + i * 128;
            int row = idx >> 3, c16 = idx & 7;
            int sw = (c16 * 4) ^ ((row & 7) << 2);
            cp16(baseB + row * 128 + sw * 4, W + (bn + row) * DMODEL + chunk * 32 + c16 * 4);
        }
    };

    load_stage(0, 0); CP_COMMIT();
    load_stage(1, 1); CP_COMMIT();

    const int NCHUNK = DMODEL / 32;   // 32
    for (int kt = 0; kt < NCHUNK; kt++) {
        CP_WAIT1();
        __syncthreads();
        if (kt + 2 < NCHUNK) load_stage(kt + 2, (kt + 2) % GNSTG);
        CP_COMMIT();

        const uint32_t* As = gsm + (kt % GNSTG) * (GSTGB / 4);
        const uint32_t* Bs = As + 4096;

        #pragma unroll
        for (int ks = 0; ks < 4; ks++) {
            const int cc = ks * 8 + qd;
            uint32_t a[4][4];
            #pragma unroll
            for (int tm = 0; tm < 4; tm++) {
                int r0 = wm * 64 + tm * 16 + rl;
                int x0 = cc ^ ((r0 & 7) << 2);
                int x1 = (cc + 4) ^ ((r0 & 7) << 2);
                const uint32_t* p0 = As + r0 * 32;
                const uint32_t* p1 = p0 + 8 * 32;
                a[tm][0] = p0[x0]; a[tm][1] = p1[x0];
                a[tm][2] = p0[x1]; a[tm][3] = p1[x1];
            }
            #pragma unroll
            for (int tn = 0; tn < 8; tn++) {
                int r = wn * 64 + tn * 8 + rl;
                int x0 = cc ^ ((r & 7) << 2);
                int x1 = (cc + 4) ^ ((r & 7) << 2);
                uint32_t b[2] = { Bs[r * 32 + x0], Bs[r * 32 + x1] };
                #pragma unroll
                for (int tm = 0; tm < 4; tm++)
                    mma_tf32(c[tm][tn], a[tm], b);
            }
        }
    }

    // ---- epilogue ----
    if (round_out) {
        #pragma unroll
        for (int tm = 0; tm < 4; tm++) {
            size_t r0 = bm + wm * 64 + tm * 16 + rl;
            #pragma unroll
            for (int tn = 0; tn < 8; tn++) {
                int col = (int)bn + wn * 64 + tn * 8 + (qd << 1);
                *(float2*)&C[r0 * Nout + col] = make_float2(
                    __uint_as_float(f2tf(c[tm][tn][0])), __uint_as_float(f2tf(c[tm][tn][1])));
                *(float2*)&C[(r0 + 8) * Nout + col] = make_float2(
                    __uint_as_float(f2tf(c[tm][tn][2])), __uint_as_float(f2tf(c[tm][tn][3])));
            }
        }
    } else {
        #pragma unroll
        for (int tm = 0; tm < 4; tm++) {
            size_t r0 = bm + wm * 64 + tm * 16 + rl;
            #pragma unroll
            for (int tn = 0; tn < 8; tn++) {
                int col = (int)bn + wn * 64 + tn * 8 + (qd << 1);
                *(float2*)&C[r0 * Nout + col]       = make_float2(c[tm][tn][0], c[tm][tn][1]);
                *(float2*)&C[(r0 + 8) * Nout + col] = make_float2(c[tm][tn][2], c[tm][tn][3]);
            }
        }
    }
}

// ============================================================================
// Fused flash attention. Block = (b, h, 128 query rows). 128 threads, 4 warps.
// Warp w owns 32 rows. Bc = 64, dh = 64. qkv pre-rounded tf32: no cvt needed.
// Q via cp.async. K double-buffered. DEDICATED 128-row P buffer (R5 bug fix).
// SMEM words: Q[0,8192) K0[8192,12288) K1[12288,16384) V[16384,20480) P[20480,28672)
// ============================================================================
#define ATT_SMEM (28672 * 4)   // 114688 B; 2 CTAs/SM (224KB <= 228KB)

__global__ __launch_bounds__(128) void attn_kernel(
    const float* __restrict__ qkv, const float* __restrict__ bias,
    const float* __restrict__ beta, float* __restrict__ attn_out)
{
    extern __shared__ uint32_t smx[];
    uint32_t* Qs = smx;
    uint32_t* Ps = smx + 20480;
    const uint32_t sb = smem_u32(smx);
    const uint32_t kAddr[2] = { sb + 8192 * 4, sb + 12288 * 4 };
    const uint32_t vAddr = sb + 16384 * 4;

    const int tid  = threadIdx.x;
    const int lane = tid & 31;
    const int warp = tid >> 5;
    const int rl   = lane >> 2;
    const int qd   = lane & 3;
    const int h    = blockIdx.y;
    const int b    = blockIdx.z;
    const int row0g = blockIdx.x * 128;

    const bool usebias = (h < NPHYS);
    const float betah  = usebias ? beta[h] : 0.f;
    const float scale  = 0.125f;

    const float* kvbase = qkv + (size_t)b * SEQ * 3072 + h * 64;
    const float* qbase  = qkv + ((size_t)(b * SEQ + row0g)) * 3072 + h * 64;

    // K/V tile loader: 64 rows x 64 words; 1024 16B-chunks; 8 per thread.
    auto load_kv = [&](const float* src, uint32_t dstBase, int shift) {
        #pragma unroll
        for (int i = 0; i < 8; i++) {
            int idx = tid + i * 128;
            int row = idx >> 4, c16 = idx & 15;
            int sw = (c16 * 4) ^ ((row & 7) << shift);
            cp16(dstBase + (row * 64 + sw) * 4, src + (size_t)row * 3072 + c16 * 4);
        }
    };

    // prologue: Q (128x64), then K(0)
    #pragma unroll
    for (int i = 0; i < 16; i++) {
        int idx = tid + i * 128;
        int row = idx >> 4, c16 = idx & 15;
        int sw = (c16 * 4) ^ ((row & 7) << 2);
        cp16(sb + (row * 64 + sw) * 4, qbase + (size_t)row * 3072 + c16 * 4);
    }
    CP_COMMIT();
    load_kv(kvbase + 1024, kAddr[0], 2); CP_COMMIT();

    float o[2][8][4];
    #pragma unroll
    for (int tm = 0; tm < 2; tm++)
        #pragma unroll
        for (int tn = 0; tn < 8; tn++)
            #pragma unroll
            for (int i = 0; i < 4; i++) o[tm][tn][i] = 0.f;
    float m[2][2] = {{-1e30f, -1e30f}, {-1e30f, -1e30f}};
    float l[2][2] = {{0.f, 0.f}, {0.f, 0.f}};

    for (int jt = 0; jt < 32; jt++) {
        __syncthreads();   // prev iter's V/P reads done before reissuing loads

        // issue V(jt), then K(jt+1)
        load_kv(kvbase + (size_t)jt * 64 * 3072 + 2048, vAddr, 3); CP_COMMIT();
        if (jt + 1 < 32) load_kv(kvbase + (size_t)(jt + 1) * 64 * 3072 + 1024, kAddr[(jt + 1) & 1], 2);
        CP_COMMIT();

        CP_WAIT2();        // K(jt) ready (and Q at jt=0)
        __syncthreads();

        const uint32_t* Ks = smx + 8192 + (jt & 1) * 4096;

        // ---- S = Q K^T (warp tile 32x64) ----
        float s[2][8][4];
        #pragma unroll
        for (int tm = 0; tm < 2; tm++)
            #pragma unroll
            for (int tn = 0; tn < 8; tn++)
                #pragma unroll
                for (int i = 0; i < 4; i++) s[tm][tn][i] = 0.f;

        #pragma unroll
        for (int ks = 0; ks < 8; ks++) {
            const int cc = ks * 8 + qd;
            const int xq0 = cc ^ (rl << 2), xq1 = (cc + 4) ^ (rl << 2);
            uint32_t a0[4], a1[4];
            {
                int r0 = warp * 32 + rl;
                a0[0] = Qs[r0 * 64 + xq0];        a0[1] = Qs[(r0 + 8) * 64 + xq0];
                a0[2] = Qs[r0 * 64 + xq1];        a0[3] = Qs[(r0 + 8) * 64 + xq1];
                a1[0] = Qs[(r0 + 16) * 64 + xq0]; a1[1] = Qs[(r0 + 24) * 64 + xq0];
                a1[2] = Qs[(r0 + 16) * 64 + xq1]; a1[3] = Qs[(r0 + 24) * 64 + xq1];
            }
            #pragma unroll
            for (int tn = 0; tn < 8; tn++) {
                int kr = tn * 8 + rl;
                uint32_t bb[2] = { Ks[kr * 64 + xq0], Ks[kr * 64 + xq1] };
                mma_tf32(s[0][tn], a0, bb);
                mma_tf32(s[1][tn], a1, bb);
            }
        }

        // ---- scale + bias ----
        #pragma unroll
        for (int tm = 0; tm < 2; tm++) {
            if (usebias) {
                int grow = row0g + warp * 32 + tm * 16 + rl;
                const float* bb0 = bias + ((size_t)b * SEQ + grow) * SEQ + jt * 64;
                const float* bb1 = bb0 + (size_t)8 * SEQ;
                #pragma unroll
                for (int tn = 0; tn < 8; tn++) {
                    int col = tn * 8 + (qd << 1);
                    float2 x0 = *(const float2*)&bb0[col];
                    float2 x1 = *(const float2*)&bb1[col];
                    s[tm][tn][0] = s[tm][tn][0] * scale + betah * x0.x;
                    s[tm][tn][1] = s[tm][tn][1] * scale + betah * x0.y;
                    s[tm][tn][2] = s[tm][tn][2] * scale + betah * x1.x;
                    s[tm][tn][3] = s[tm][tn][3] * scale + betah * x1.y;
                }
            } else {
                #pragma unroll
                for (int tn = 0; tn < 8; tn++)
                    #pragma unroll
                    for (int i = 0; i < 4; i++) s[tm][tn][i] *= scale;
            }
        }

        // ---- online softmax ----
        #pragma unroll
        for (int tm = 0; tm < 2; tm++) {
            float mx0 = -1e30f, mx1 = -1e30f;
            #pragma unroll
            for (int tn = 0; tn < 8; tn++) {
                mx0 = fmaxf(mx0, fmaxf(s[tm][tn][0], s[tm][tn][1]));
                mx1 = fmaxf(mx1, fmaxf(s[tm][tn][2], s[tm][tn][3]));
            }
            mx0 = fmaxf(mx0, __shfl_xor_sync(0xffffffffu, mx0, 1));
            mx0 = fmaxf(mx0, __shfl_xor_sync(0xffffffffu, mx0, 2));
            mx1 = fmaxf(mx1, __shfl_xor_sync(0xffffffffu, mx1, 1));
            mx1 = fmaxf(mx1, __shfl_xor_sync(0xffffffffu, mx1, 2));

            float mn0 = fmaxf(m[tm][0], mx0), mn1 = fmaxf(m[tm][1], mx1);
            float f0 = __expf(m[tm][0] - mn0), f1 = __expf(m[tm][1] - mn1);
            float sum0 = 0.f, sum1 = 0.f;
            #pragma unroll
            for (int tn = 0; tn < 8; tn++) {
                s[tm][tn][0] = __expf(s[tm][tn][0] - mn0);
                s[tm][tn][1] = __expf(s[tm][tn][1] - mn0);
                s[tm][tn][2] = __expf(s[tm][tn][2] - mn1);
                s[tm][tn][3] = __expf(s[tm][tn][3] - mn1);
                sum0 += s[tm][tn][0] + s[tm][tn][1];
                sum1 += s[tm][tn][2] + s[tm][tn][3];
            }
            sum0 += __shfl_xor_sync(0xffffffffu, sum0, 1);
            sum0 += __shfl_xor_sync(0xffffffffu, sum0, 2);
            sum1 += __shfl_xor_sync(0xffffffffu, sum1, 1);
            sum1 += __shfl_xor_sync(0xffffffffu, sum1, 2);
            l[tm][0] = l[tm][0] * f0 + sum0;
            l[tm][1] = l[tm][1] * f1 + sum1;
            m[tm][0] = mn0; m[tm][1] = mn1;
            #pragma unroll
            for (int tn = 0; tn < 8; tn++) {
                o[tm][tn][0] *= f0; o[tm][tn][1] *= f0;
                o[tm][tn][2] *= f1; o[tm][tn][3] *= f1;
            }
        }

        // ---- stage P (C-frag -> SMEM, warp-private rows, dedicated buffer) ----
        #pragma unroll
        for (int tm = 0; tm < 2; tm++) {
            int pr = warp * 32 + tm * 16 + rl;
            #pragma unroll
            for (int tn = 0; tn < 8; tn++) {
                int x = (tn * 8 + (qd << 1)) ^ (rl << 2);
                *(uint2*)&Ps[pr * 64 + x]       = make_uint2(f2tf(s[tm][tn][0]), f2tf(s[tm][tn][1]));
                *(uint2*)&Ps[(pr + 8) * 64 + x] = make_uint2(f2tf(s[tm][tn][2]), f2tf(s[tm][tn][3]));
            }
        }
        __syncwarp();

        CP_WAIT1();        // V(jt) complete (K(jt+1) may pend)
        __syncthreads();

        const uint32_t* Vs = smx + 16384;

        // ---- O += P V ----
        #pragma unroll
        for (int ks = 0; ks < 8; ks++) {
            const int cc = ks * 8 + qd;
            const int xp0 = cc ^ (rl << 2), xp1 = (cc + 4) ^ (rl << 2);
            uint32_t a0[4], a1[4];
            {
                int r0 = warp * 32 + rl;
                a0[0] = Ps[r0 * 64 + xp0];        a0[1] = Ps[(r0 + 8) * 64 + xp0];
                a0[2] = Ps[r0 * 64 + xp1];        a0[3] = Ps[(r0 + 8) * 64 + xp1];
                a1[0] = Ps[(r0 + 16) * 64 + xp0]; a1[1] = Ps[(r0 + 24) * 64 + xp0];
                a1[2] = Ps[(r0 + 16) * 64 + xp1]; a1[3] = Ps[(r0 + 24) * 64 + xp1];
            }
            #pragma unroll
            for (int tn = 0; tn < 8; tn++) {
                int dh = tn * 8 + rl;
                uint32_t bb[2];
                bb[0] = Vs[cc * 64 + (dh ^ (qd << 3))];
                bb[1] = Vs[(cc + 4) * 64 + (dh ^ (((qd + 4) & 7) << 3))];
                mma_tf32(o[0][tn], a0, bb);
                mma_tf32(o[1][tn], a1, bb);
            }
        }
    }

    // ---- epilogue: O / l (tf32-rounded for the raw-fed proj GEMM) ----
    #pragma unroll
    for (int tm = 0; tm < 2; tm++) {
        float inv0 = 1.f / l[tm][0], inv1 = 1.f / l[tm][1];
        int grow = row0g + warp * 32 + tm * 16 + rl;
        float* ob = attn_out + ((size_t)(b * SEQ + grow)) * 1024 + h * 64;
        #pragma unroll
        for (int tn = 0; tn < 8; tn++) {
            int col = tn * 8 + (qd << 1);
            *(float2*)&ob[col] = make_float2(
                __uint_as_float(f2tf(o[tm][tn][0] * inv0)),
                __uint_as_float(f2tf(o[tm][tn][1] * inv0)));
            *(float2*)&ob[(size_t)8 * 1024 + col] = make_float2(
                __uint_as_float(f2tf(o[tm][tn][2] * inv1)),
                __uint_as_float(f2tf(o[tm][tn][3] * inv1)));
        }
    }
}

// ============================================================================
// Launch
// ============================================================================
extern "C" void kernel_launch(void* const* d_in, const int* in_sizes, int n_in,
                              void* d_out, int out_size)
{
    const float* x     = (const float*)d_in[0];
    const float* bias  = (const float*)d_in[1];
    const float* Wqkv  = (const float*)d_in[2];
    const float* Wproj = (const float*)d_in[3];
    const float* beta  = (const float*)d_in[4];
    float* out = (float*)d_out;

    float *qkv_ptr, *att_ptr, *xr, *wqkvr, *wprojr;
    cudaGetSymbolAddress((void**)&qkv_ptr, g_qkv);
    cudaGetSymbolAddress((void**)&att_ptr, g_att);
    cudaGetSymbolAddress((void**)&xr, g_xr);
    cudaGetSymbolAddress((void**)&wqkvr, g_wqkvr);
    cudaGetSymbolAddress((void**)&wprojr, g_wprojr);

    cudaFuncSetAttribute(gemm_ws_kernel,
                         cudaFuncAttributeMaxDynamicSharedMemorySize, GEMM_SMEM);
    cudaFuncSetAttribute(attn_kernel,
                         cudaFuncAttributeMaxDynamicSharedMemorySize, ATT_SMEM);

    // 0) pre-round GEMM operands to tf32 (RNA) — GEMMs then feed raw bits
    {
        int n4;
        n4 = MTOK * DMODEL / 4;
        round_tf32_kernel<<<(n4 + 255) / 256, 256>>>(x, xr, n4);
        n4 = 3 * DMODEL * DMODEL / 4;
        round_tf32_kernel<<<(n4 + 255) / 256, 256>>>(Wqkv, wqkvr, n4);
        n4 = DMODEL * DMODEL / 4;
        round_tf32_kernel<<<(n4 + 255) / 256, 256>>>(Wproj, wprojr, n4);
    }

    // 1) qkv = x @ Wqkv^T   [8192, 3072], tf32-rounded output
    gemm_ws_kernel<<<dim3(MTOK / 128, 3 * DMODEL / 128), 128, GEMM_SMEM>>>(
        xr, wqkvr, qkv_ptr, 3 * DMODEL, 1);

    // 2) fused attention -> [B, N, H*dh]
    attn_kernel<<<dim3(SEQ / 128, 16, B_SZ), 128, ATT_SMEM>>>(qkv_ptr, bias, beta, att_ptr);

    // 3) out = attn @ Wproj^T   [8192, 1024], full-precision output
    gemm_ws_kernel<<<dim3(MTOK / 128, DMODEL / 128), 128, GEMM_SMEM>>>(
        att_ptr, wprojr, out, DMODEL, 0);
}